// round 2
// baseline (speedup 1.0000x reference)
#include <cuda_runtime.h>
#include <math.h>

#define NND 100000
#define D 128
#define NELEM (NND*D)
#define EMAX 2000000
#define NBLK 98           // ceil(100000/1024)

// Scratch (allocation-free)
__device__ float  g_buf0[NELEM];
__device__ float  g_buf1[NELEM];
__device__ double g_sum[3];
__device__ double g_sumsq[3];
__device__ int    g_deg[NND + 1];
__device__ int    g_off[NND + 1];
__device__ int    g_cursor[NND];
__device__ int    g_srcs[EMAX];
__device__ int    g_blocksum[128];
__device__ int    g_blockoff[128];

#define PACK2(d, f)  asm("mov.b64 %0, {%1, %1};" : "=l"(d) : "f"(f))
#define UNPACK2(lo, hi, d) asm("mov.b64 {%0, %1}, %2;" : "=f"(lo), "=f"(hi) : "l"(d))
#define FMA2(d, a, b) asm("fma.rn.f32x2 %0, %1, %2, %3;" : "=l"(d) : "l"(a), "l"(b), "l"(d))

// ---------------- CSR build ----------------

__global__ void k_zero() {
    int i = blockIdx.x * blockDim.x + threadIdx.x;
    if (i <= NND) g_deg[i] = 0;
    if (i < 3) { g_sum[i] = 0.0; g_sumsq[i] = 0.0; }
}

__global__ void k_count(const int* __restrict__ ei, int E) {
    int e = blockIdx.x * blockDim.x + threadIdx.x;
    if (e < E) atomicAdd(&g_deg[__ldg(ei + E + e)], 1);
}

__global__ void __launch_bounds__(1024) k_scan1() {
    __shared__ int s[1024];
    int t = threadIdx.x;
    int i = blockIdx.x * 1024 + t;
    int v = (i < NND) ? g_deg[i] : 0;
    s[t] = v;
    __syncthreads();
    #pragma unroll
    for (int o = 1; o < 1024; o <<= 1) {
        int add = (t >= o) ? s[t - o] : 0;
        __syncthreads();
        s[t] += add;
        __syncthreads();
    }
    if (i <= NND) g_off[i] = s[t] - v;   // exclusive within block
    if (t == 1023) g_blocksum[blockIdx.x] = s[t];
}

__global__ void __launch_bounds__(128) k_scan2() {
    __shared__ int s[128];
    int t = threadIdx.x;
    int v = (t < NBLK) ? g_blocksum[t] : 0;
    s[t] = v;
    __syncthreads();
    #pragma unroll
    for (int o = 1; o < 128; o <<= 1) {
        int add = (t >= o) ? s[t - o] : 0;
        __syncthreads();
        s[t] += add;
        __syncthreads();
    }
    g_blockoff[t] = s[t] - v;            // exclusive block offsets
}

__global__ void k_scan3(int E) {
    int i = blockIdx.x * blockDim.x + threadIdx.x;
    if (i < NND) {
        int off = g_off[i] + g_blockoff[i >> 10];
        g_off[i] = off;
        g_cursor[i] = off;
    }
    if (i == 0) g_off[NND] = E;
}

__global__ void k_fill(const int* __restrict__ ei, int E) {
    int e = blockIdx.x * blockDim.x + threadIdx.x;
    if (e >= E) return;
    int dst = __ldg(ei + E + e);
    int src = __ldg(ei + e);
    int pos = atomicAdd(&g_cursor[dst], 1);
    g_srcs[pos] = src;
}

// h[n] = (1+eps)*node[n] + sum_{e: dst=n} node[src[e]]. Warp per node.
__global__ void __launch_bounds__(256) k_aggr(const float* __restrict__ node,
                                              const float* __restrict__ eps_p,
                                              float* __restrict__ h) {
    int warp = (blockIdx.x * blockDim.x + threadIdx.x) >> 5;
    int lane = threadIdx.x & 31;
    if (warp >= NND) return;
    int n = warp;
    float s = 1.0f + __ldg(eps_p);
    const float4* nodes = (const float4*)node;
    float4 acc = __ldg(nodes + (long long)n * 32 + lane);
    acc.x *= s; acc.y *= s; acc.z *= s; acc.w *= s;
    int j   = g_off[n];
    int end = g_off[n + 1];
    for (; j + 4 <= end; j += 4) {
        int s0 = __ldg(&g_srcs[j + 0]);
        int s1 = __ldg(&g_srcs[j + 1]);
        int s2 = __ldg(&g_srcs[j + 2]);
        int s3 = __ldg(&g_srcs[j + 3]);
        float4 v0 = __ldg(nodes + (long long)s0 * 32 + lane);
        float4 v1 = __ldg(nodes + (long long)s1 * 32 + lane);
        float4 v2 = __ldg(nodes + (long long)s2 * 32 + lane);
        float4 v3 = __ldg(nodes + (long long)s3 * 32 + lane);
        acc.x += v0.x + v1.x + v2.x + v3.x;
        acc.y += v0.y + v1.y + v2.y + v3.y;
        acc.z += v0.z + v1.z + v2.z + v3.z;
        acc.w += v0.w + v1.w + v2.w + v3.w;
    }
    for (; j < end; ++j) {
        int s0 = __ldg(&g_srcs[j]);
        float4 v0 = __ldg(nodes + (long long)s0 * 32 + lane);
        acc.x += v0.x; acc.y += v0.y; acc.z += v0.z; acc.w += v0.w;
    }
    ((float4*)h)[(long long)n * 32 + lane] = acc;
}

// ---------------- GEMM ----------------
// Y = op(A) @ W + bias ; op = identity or relu(graph_ln(A)).
// 128x128 tile, 256 threads, 8x8 micro-tile, FFMA2 accumulation.
// B tile is pre-duplicated into packed (b,b) 64-bit pairs in smem so the
// inner loop is pure LDS.128 + FFMA2 (no mov.b64 in the hot path).
template<bool APPLY>
__global__ void __launch_bounds__(256)
k_gemm(const float* __restrict__ A, const float* __restrict__ W,
       const float* __restrict__ bias,
       const float* __restrict__ lnw, const float* __restrict__ lnb,
       int sidx_in, int sidx_out,
       float* __restrict__ Y, int M)
{
    __shared__ float As[16][132];
    __shared__ unsigned long long Bs2[16][128];
    __shared__ float s_bias[128];
    __shared__ float s_lnw[128];
    __shared__ float s_lnb[128];

    const int t  = threadIdx.x;
    const int tx = t & 15;
    const int ty = t >> 4;
    const int row0 = blockIdx.x * 128;

    if (t < 128) {
        s_bias[t] = bias[t];
        if (APPLY) { s_lnw[t] = lnw[t]; s_lnb[t] = lnb[t]; }
    }
    float mu = 0.f, inv = 0.f;
    if (APPLY) {
        double m = g_sum[sidx_in] * (1.0 / (double)NELEM);
        double v = g_sumsq[sidx_in] * (1.0 / (double)NELEM) - m * m;
        if (v < 0.0) v = 0.0;
        mu  = (float)m;
        inv = 1.0f / (sqrtf((float)v) + 1e-5f);
    }
    __syncthreads();

    unsigned long long acc[4][8];
    #pragma unroll
    for (int i = 0; i < 4; ++i)
        #pragma unroll
        for (int j = 0; j < 8; ++j) acc[i][j] = 0ULL;

    for (int kb = 0; kb < 128; kb += 16) {
        // A tile, LN+ReLU fused, transposed store.
        #pragma unroll
        for (int it = 0; it < 2; ++it) {
            int idx = t + it * 256;
            int r   = idx >> 2;
            int c4  = idx & 3;
            int grow = row0 + r;
            float4 v = make_float4(0.f, 0.f, 0.f, 0.f);
            if (grow < M) v = __ldg((const float4*)(A + (long long)grow * D + kb) + c4);
            if (APPLY) {
                int k0 = kb + c4 * 4;
                v.x = fmaxf((v.x - mu) * inv * s_lnw[k0+0] + s_lnb[k0+0], 0.f);
                v.y = fmaxf((v.y - mu) * inv * s_lnw[k0+1] + s_lnb[k0+1], 0.f);
                v.z = fmaxf((v.z - mu) * inv * s_lnw[k0+2] + s_lnb[k0+2], 0.f);
                v.w = fmaxf((v.w - mu) * inv * s_lnw[k0+3] + s_lnb[k0+3], 0.f);
            }
            As[c4*4+0][r] = v.x;
            As[c4*4+1][r] = v.y;
            As[c4*4+2][r] = v.z;
            As[c4*4+3][r] = v.w;
        }
        // B tile, duplicated into (b,b) pairs at store time.
        #pragma unroll
        for (int it = 0; it < 2; ++it) {
            int idx = t + it * 256;
            int kr  = idx >> 5;
            int c4  = idx & 31;
            float4 v = __ldg((const float4*)(W + (long long)(kb + kr) * D) + c4);
            unsigned long long d0, d1, d2, d3;
            PACK2(d0, v.x); PACK2(d1, v.y); PACK2(d2, v.z); PACK2(d3, v.w);
            ulonglong2* dp = (ulonglong2*)&Bs2[kr][c4 * 4];
            dp[0] = make_ulonglong2(d0, d1);
            dp[1] = make_ulonglong2(d2, d3);
        }
        __syncthreads();

        #pragma unroll
        for (int k = 0; k < 16; ++k) {
            const ulonglong2* ap = (const ulonglong2*)&As[k][ty * 8];
            ulonglong2 a01 = ap[0], a23 = ap[1];
            const ulonglong2* bpA = (const ulonglong2*)&Bs2[k][tx * 4];
            const ulonglong2* bpB = (const ulonglong2*)&Bs2[k][64 + tx * 4];
            ulonglong2 b01 = bpA[0], b23 = bpA[1];
            ulonglong2 b45 = bpB[0], b67 = bpB[1];
            unsigned long long bd[8] = {b01.x, b01.y, b23.x, b23.y,
                                        b45.x, b45.y, b67.x, b67.y};
            #pragma unroll
            for (int j = 0; j < 8; ++j) {
                FMA2(acc[0][j], a01.x, bd[j]);
                FMA2(acc[1][j], a01.y, bd[j]);
                FMA2(acc[2][j], a23.x, bd[j]);
                FMA2(acc[3][j], a23.y, bd[j]);
            }
        }
        __syncthreads();
    }

    // Epilogue: bias, store, LN partial sums.
    float lsum = 0.f, lsq = 0.f;
    #pragma unroll
    for (int ri = 0; ri < 4; ++ri) {
        float lo[8], hi[8];
        #pragma unroll
        for (int j = 0; j < 8; ++j) UNPACK2(lo[j], hi[j], acc[ri][j]);
        #pragma unroll
        for (int p = 0; p < 2; ++p) {
            int grow = row0 + ty * 8 + ri * 2 + p;
            if (grow < M) {
                float c[8];
                #pragma unroll
                for (int j = 0; j < 8; ++j) {
                    int col = (j < 4) ? (tx * 4 + j) : (64 + tx * 4 + j - 4);
                    float val = (p == 0 ? lo[j] : hi[j]) + s_bias[col];
                    c[j] = val;
                    lsum += val;
                    lsq  += val * val;
                }
                *(float4*)(Y + (long long)grow * D + tx * 4)      = make_float4(c[0], c[1], c[2], c[3]);
                *(float4*)(Y + (long long)grow * D + 64 + tx * 4) = make_float4(c[4], c[5], c[6], c[7]);
            }
        }
    }
    #pragma unroll
    for (int o = 16; o > 0; o >>= 1) {
        lsum += __shfl_down_sync(0xffffffffu, lsum, o);
        lsq  += __shfl_down_sync(0xffffffffu, lsq, o);
    }
    if ((t & 31) == 0) {
        atomicAdd(&g_sum[sidx_out],   (double)lsum);
        atomicAdd(&g_sumsq[sidx_out], (double)lsq);
    }
}

// out = relu(graph_layernorm(Y)), sums at index 2.
__global__ void k_apply_out(const float* __restrict__ Y, const float* __restrict__ w,
                            const float* __restrict__ b, float* __restrict__ out) {
    long long i = blockIdx.x * (long long)blockDim.x + threadIdx.x;
    if (i >= NELEM/4) return;
    double m = g_sum[2] * (1.0 / (double)NELEM);
    double v = g_sumsq[2] * (1.0 / (double)NELEM) - m * m;
    if (v < 0.0) v = 0.0;
    float mu  = (float)m;
    float inv = 1.0f / (sqrtf((float)v) + 1e-5f);
    int k = ((int)i * 4) & 127;
    float4 val = __ldg((const float4*)Y + i);
    float4 o;
    o.x = fmaxf((val.x - mu) * inv * __ldg(w + k + 0) + __ldg(b + k + 0), 0.f);
    o.y = fmaxf((val.y - mu) * inv * __ldg(w + k + 1) + __ldg(b + k + 1), 0.f);
    o.z = fmaxf((val.z - mu) * inv * __ldg(w + k + 2) + __ldg(b + k + 2), 0.f);
    o.w = fmaxf((val.w - mu) * inv * __ldg(w + k + 3) + __ldg(b + k + 3), 0.f);
    ((float4*)out)[i] = o;
}

extern "C" void kernel_launch(void* const* d_in, const int* in_sizes, int n_in,
                              void* d_out, int out_size) {
    const float* node = (const float*)d_in[0];
    const int*   ei   = (const int*)d_in[1];
    const float* eps  = (const float*)d_in[4];
    const float* W1   = (const float*)d_in[5];
    const float* b1   = (const float*)d_in[6];
    const float* ln1w = (const float*)d_in[7];
    const float* ln1b = (const float*)d_in[8];
    const float* W2   = (const float*)d_in[9];
    const float* b2   = (const float*)d_in[10];
    const float* ln2w = (const float*)d_in[11];
    const float* ln2b = (const float*)d_in[12];
    const float* W3   = (const float*)d_in[13];
    const float* b3   = (const float*)d_in[14];
    const float* lnow = (const float*)d_in[15];
    const float* lnob = (const float*)d_in[16];

    int E = in_sizes[1] / 2;

    void *p0, *p1;
    cudaGetSymbolAddress(&p0, g_buf0);
    cudaGetSymbolAddress(&p1, g_buf1);
    float* buf0 = (float*)p0;
    float* buf1 = (float*)p1;

    // CSR build
    k_zero<<<(NND + 1024) / 1024, 1024>>>();
    k_count<<<(E + 255) / 256, 256>>>(ei, E);
    k_scan1<<<NBLK, 1024>>>();
    k_scan2<<<1, 128>>>();
    k_scan3<<<(NND + 255) / 256, 256>>>(E);
    k_fill<<<(E + 255) / 256, 256>>>(ei, E);

    // Aggregation: h = (1+eps)*node + gather-sum
    k_aggr<<<(NND * 32 + 255) / 256, 256>>>(node, eps, buf0);

    int gblocks = (NND + 127) / 128;
    k_gemm<false><<<gblocks, 256>>>(buf0, W1, b1, nullptr, nullptr, 0, 0, buf1, NND);
    k_gemm<true> <<<gblocks, 256>>>(buf1, W2, b2, ln1w, ln1b, 0, 1, buf0, NND);
    k_gemm<true> <<<gblocks, 256>>>(buf0, W3, b3, ln2w, ln2b, 1, 2, buf1, NND);

    int nb_elem = (NELEM/4 + 255) / 256;
    k_apply_out<<<nb_elem, 256>>>(buf1, lnow, lnob, (float*)d_out);
}